// round 1
// baseline (speedup 1.0000x reference)
#include <cuda_runtime.h>

#define NN 50000
#define NE 800000
#define DIM 256
#define GF 200
#define NG 512

// Scratch (allocation-free rule: __device__ globals)
__device__ float g_bufA[(size_t)NN * DIM];
__device__ float g_bufB[(size_t)NN * DIM];
__device__ float g_gsum[NG * GF];

enum { M_PLAIN = 0, M_COMBINE = 1, M_RELU = 2, M_READOUT = 3 };

__device__ __forceinline__ float relu_f(float x) { return x > 0.f ? x : 0.f; }

// ---------------------------------------------------------------------------
// Tiled fp32 GEMM: C[M,N] = epilogue(A[M,256] @ B[256,N])
// BM=64, BN=64, BK=16, 256 threads, 4x4 micro-tile per thread.
// ---------------------------------------------------------------------------
template <int MODE>
__global__ __launch_bounds__(256)
void gemm_k(const float* __restrict__ A, const float* __restrict__ B,
            const float* __restrict__ bias,   // [N]     (COMBINE: br for GEMM branch; RELU/READOUT: bias)
            const float* __restrict__ other,  // [M,N]   (COMBINE: agg)
            const float* __restrict__ bias2,  // [N]     (COMBINE: b for agg branch)
            const int* __restrict__ gid,      // [M]     (READOUT)
            float* __restrict__ C, int M, int N)
{
    const int K = 256;
    const int BM = 64, BN = 64, BK = 16;

    __shared__ float As[BK][BM];   // transposed: As[k][m]
    __shared__ float Bs[BK][BN];

    int tid = threadIdx.x;
    int tx = tid & 15;     // col group 0..15
    int ty = tid >> 4;     // row group 0..15
    int rowBase = blockIdx.y * BM;
    int colBase = blockIdx.x * BN;

    // A tile load mapping: thread -> (aRow 0..63, aCol 0/4/8/12), float4
    int aRow = tid >> 2;
    int aCol = (tid & 3) * 4;
    // B tile load mapping: thread -> (bRow 0..15, bCol 0..60 step 4), float4
    int bRow = tid >> 4;
    int bCol = (tid & 15) * 4;

    bool aValid = (rowBase + aRow) < M;
    const float* Aptr = A + (size_t)(rowBase + aRow) * K;

    float acc[4][4] = {};

    for (int k0 = 0; k0 < K; k0 += BK) {
        float4 av = make_float4(0.f, 0.f, 0.f, 0.f);
        if (aValid) av = *(const float4*)(Aptr + k0 + aCol);
        As[aCol + 0][aRow] = av.x;
        As[aCol + 1][aRow] = av.y;
        As[aCol + 2][aRow] = av.z;
        As[aCol + 3][aRow] = av.w;

        float4 bv = make_float4(0.f, 0.f, 0.f, 0.f);
        int bc = colBase + bCol;
        const float* Brow = B + (size_t)(k0 + bRow) * N;
        if (bc + 3 < N) {
            bv = *(const float4*)(Brow + bc);
        } else {
            if (bc + 0 < N) bv.x = Brow[bc + 0];
            if (bc + 1 < N) bv.y = Brow[bc + 1];
            if (bc + 2 < N) bv.z = Brow[bc + 2];
            if (bc + 3 < N) bv.w = Brow[bc + 3];
        }
        *(float4*)&Bs[bRow][bCol] = bv;

        __syncthreads();

        #pragma unroll
        for (int kk = 0; kk < BK; kk++) {
            float4 a = *(const float4*)&As[kk][ty * 4];
            float4 b = *(const float4*)&Bs[kk][tx * 4];
            float avv[4] = {a.x, a.y, a.z, a.w};
            float bvv[4] = {b.x, b.y, b.z, b.w};
            #pragma unroll
            for (int i = 0; i < 4; i++)
                #pragma unroll
                for (int j = 0; j < 4; j++)
                    acc[i][j] += avv[i] * bvv[j];
        }
        __syncthreads();
    }

    int c = colBase + tx * 4;
    #pragma unroll
    for (int i = 0; i < 4; i++) {
        int r = rowBase + ty * 4 + i;
        if (r >= M) continue;

        if (MODE == M_PLAIN) {
            float4 v = make_float4(acc[i][0], acc[i][1], acc[i][2], acc[i][3]);
            *(float4*)(C + (size_t)r * N + c) = v;
        } else if (MODE == M_COMBINE) {
            float4 bb = *(const float4*)(bias + c);
            float4 b2 = *(const float4*)(bias2 + c);
            float4 o  = *(const float4*)(other + (size_t)r * N + c);
            float4 v;
            v.x = relu_f(acc[i][0] + bb.x) + relu_f(o.x + b2.x);
            v.y = relu_f(acc[i][1] + bb.y) + relu_f(o.y + b2.y);
            v.z = relu_f(acc[i][2] + bb.z) + relu_f(o.z + b2.z);
            v.w = relu_f(acc[i][3] + bb.w) + relu_f(o.w + b2.w);
            *(float4*)(C + (size_t)r * N + c) = v;
        } else if (MODE == M_RELU) {
            float4 bb = *(const float4*)(bias + c);
            float4 v;
            v.x = relu_f(acc[i][0] + bb.x);
            v.y = relu_f(acc[i][1] + bb.y);
            v.z = relu_f(acc[i][2] + bb.z);
            v.w = relu_f(acc[i][3] + bb.w);
            *(float4*)(C + (size_t)r * N + c) = v;
        } else { // M_READOUT: y = acc + bias; gsum[gid[r]] += y  (N = 200)
            int g = gid[r];
            float* dstp = C + (size_t)g * N;
            if (c + 3 < N) {
                float4 bb = *(const float4*)(bias + c);
                float4 v = make_float4(acc[i][0] + bb.x, acc[i][1] + bb.y,
                                       acc[i][2] + bb.z, acc[i][3] + bb.w);
                atomicAdd((float4*)(dstp + c), v);
            } else {
                #pragma unroll
                for (int j = 0; j < 4; j++) {
                    int cc = c + j;
                    if (cc < N) atomicAdd(dstp + cc, acc[i][j] + bias[cc]);
                }
            }
        }
    }
}

// ---------------------------------------------------------------------------
// Edge scatter: agg[dst[e]] += X[src[e]]   (rows of 256 floats = 64 float4)
// One warp per edge; 2 float4 per lane.
// ---------------------------------------------------------------------------
__global__ __launch_bounds__(256)
void edge_scatter(const float4* __restrict__ X, const int* __restrict__ src,
                  const int* __restrict__ dst, float4* __restrict__ agg, int nE)
{
    int w = (int)((blockIdx.x * (size_t)blockDim.x + threadIdx.x) >> 5);
    int lane = threadIdx.x & 31;
    if (w >= nE) return;
    int s = __ldg(src + w);
    int d = __ldg(dst + w);
    const float4* xs = X + (size_t)s * 64;
    float4* ad = agg + (size_t)d * 64;
    float4 v0 = xs[lane];
    float4 v1 = xs[lane + 32];
    atomicAdd(ad + lane, v0);
    atomicAdd(ad + lane + 32, v1);
}

// ---------------------------------------------------------------------------
// Zero fill
// ---------------------------------------------------------------------------
__global__ void zero_f4(float4* __restrict__ p, int n4)
{
    int i = blockIdx.x * blockDim.x + threadIdx.x;
    int stride = gridDim.x * blockDim.x;
    float4 z = make_float4(0.f, 0.f, 0.f, 0.f);
    for (; i < n4; i += stride) p[i] = z;
}

// ---------------------------------------------------------------------------
// Final predictor: out[g] = dot(gsum[g,:], Wp) + bp   (warp per graph)
// ---------------------------------------------------------------------------
__global__ __launch_bounds__(256)
void predict_k(const float* __restrict__ gsum, const float* __restrict__ Wp,
               const float* __restrict__ bp, float* __restrict__ out)
{
    int warp = (int)((blockIdx.x * (size_t)blockDim.x + threadIdx.x) >> 5);
    int lane = threadIdx.x & 31;
    if (warp >= NG) return;
    const float* row = gsum + (size_t)warp * GF;
    float s = 0.f;
    for (int f = lane; f < GF; f += 32) s += row[f] * Wp[f];
    #pragma unroll
    for (int o = 16; o; o >>= 1) s += __shfl_xor_sync(0xffffffffu, s, o);
    if (lane == 0) out[warp] = s + bp[0];
}

// ---------------------------------------------------------------------------
extern "C" void kernel_launch(void* const* d_in, const int* in_sizes, int n_in,
                              void* d_out, int out_size)
{
    const float* nf[2]  = { (const float*)d_in[0], (const float*)d_in[2] };
    const int*   src[2] = { (const int*)d_in[4],   (const int*)d_in[7] };
    const int*   dst[2] = { (const int*)d_in[5],   (const int*)d_in[8] };
    const int*   gid[2] = { (const int*)d_in[6],   (const int*)d_in[9] };
    const float* W[2]   = { (const float*)d_in[10], (const float*)d_in[14] };
    const float* b[2]   = { (const float*)d_in[11], (const float*)d_in[15] };
    const float* Wr[2]  = { (const float*)d_in[12], (const float*)d_in[16] };
    const float* br[2]  = { (const float*)d_in[13], (const float*)d_in[17] };
    const float* Ri[2]  = { (const float*)d_in[18], (const float*)d_in[22] };
    const float* rbi[2] = { (const float*)d_in[19], (const float*)d_in[23] };
    const float* Ro[2]  = { (const float*)d_in[20], (const float*)d_in[24] };
    const float* rbo[2] = { (const float*)d_in[21], (const float*)d_in[25] };
    const float* Wp = (const float*)d_in[26];
    const float* bp = (const float*)d_in[27];
    float* out = (float*)d_out;

    float *bufA, *bufB, *gsum;
    cudaGetSymbolAddress((void**)&bufA, g_bufA);
    cudaGetSymbolAddress((void**)&bufB, g_bufB);
    cudaGetSymbolAddress((void**)&gsum, g_gsum);

    const int T = 256;
    dim3 g256(DIM / 64, (NN + 63) / 64);   // (4, 782)
    dim3 g200((GF + 63) / 64, (NN + 63) / 64);

    zero_f4<<<128, 256>>>((float4*)gsum, NG * GF / 4);

    for (int k = 0; k < 2; k++) {
        // hW = h @ W                                    -> bufA
        gemm_k<M_PLAIN><<<g256, T>>>(nf[k], W[k], nullptr, nullptr, nullptr,
                                     nullptr, bufA, NN, DIM);
        // agg = 0; agg[dst] += hW[src]                  -> bufB
        zero_f4<<<2048, 256>>>((float4*)bufB, NN * DIM / 4);
        edge_scatter<<<(NE * 32 + T - 1) / T, T>>>((const float4*)bufA, src[k],
                                                   dst[k], (float4*)bufB, NE);
        // h1 = relu(h @ Wr + br) + relu(agg + b)        -> bufA
        gemm_k<M_COMBINE><<<g256, T>>>(nf[k], Wr[k], br[k], bufB, b[k],
                                       nullptr, bufA, NN, DIM);
        // t = relu(h1 @ Ri + rbi)                       -> bufB
        gemm_k<M_RELU><<<g256, T>>>(bufA, Ri[k], rbi[k], nullptr, nullptr,
                                    nullptr, bufB, NN, DIM);
        // gsum[gid] += t @ Ro + rbo                     -> gsum (accumulated)
        gemm_k<M_READOUT><<<g200, T>>>(bufB, Ro[k], rbo[k], nullptr, nullptr,
                                       gid[k], gsum, NN, GF);
    }

    predict_k<<<(NG * 32 + 255) / 256, 256>>>(gsum, Wp, bp, out);
}

// round 3
// speedup vs baseline: 1.5137x; 1.5137x over previous
#include <cuda_runtime.h>
#include <cuda_bf16.h>
#include <cstdint>

#define NN 50000
#define NE 800000
#define DIM 256
#define GF 200
#define NG 512

// ---------------------------------------------------------------------------
// Scratch (__device__ globals; no allocations allowed)
// ---------------------------------------------------------------------------
__device__ float g_bufA[(size_t)NN * DIM];            // hW (fp32)
__device__ float g_bufB[(size_t)NN * DIM];            // agg (fp32)
__device__ __nv_bfloat16 g_Ah[(size_t)NN * DIM];      // h split hi
__device__ __nv_bfloat16 g_Al[(size_t)NN * DIM];      // h split lo
__device__ __nv_bfloat16 g_Ch[(size_t)NN * DIM];      // h1 split hi
__device__ __nv_bfloat16 g_Cl[(size_t)NN * DIM];      // h1 split lo
__device__ __nv_bfloat16 g_Wt[6 * 2 * DIM * DIM];     // transposed weight splits
__device__ float g_T[NG * DIM];                       // segment-summed t
__device__ float g_gsum[NG * GF];
__device__ int   g_cnt[NG];

enum { M_PLAIN = 0, M_COMBINE = 1, M_READOUT = 2 };

__device__ __forceinline__ float relu_f(float x) { return x > 0.f ? x : 0.f; }

__device__ __forceinline__ uint32_t smem_u32(const void* p) {
    uint32_t a;
    asm("{ .reg .u64 t; cvta.to.shared.u64 t, %1; cvt.u32.u64 %0, t; }" : "=r"(a) : "l"(p));
    return a;
}
__device__ __forceinline__ uint32_t swz(uint32_t off) { return off ^ ((off >> 3) & 0x70); }
__device__ __forceinline__ void cpa16(uint32_t s, const void* g, int sz) {
    asm volatile("cp.async.cg.shared.global [%0], [%1], 16, %2;" :: "r"(s), "l"(g), "r"(sz) : "memory");
}
__device__ __forceinline__ void ldsm4(uint32_t* r, uint32_t addr) {
    asm volatile("ldmatrix.sync.aligned.m8n8.x4.shared.b16 {%0,%1,%2,%3}, [%4];"
        : "=r"(r[0]), "=r"(r[1]), "=r"(r[2]), "=r"(r[3]) : "r"(addr));
}
__device__ __forceinline__ void mma16816(float* c, const uint32_t* a, const uint32_t* b) {
    asm volatile("mma.sync.aligned.m16n8k16.row.col.f32.bf16.bf16.f32 "
        "{%0,%1,%2,%3}, {%4,%5,%6,%7}, {%8,%9}, {%0,%1,%2,%3};"
        : "+f"(c[0]), "+f"(c[1]), "+f"(c[2]), "+f"(c[3])
        : "r"(a[0]), "r"(a[1]), "r"(a[2]), "r"(a[3]), "r"(b[0]), "r"(b[1]));
}

// ---------------------------------------------------------------------------
// HMMA GEMM: out = epilogue(A[M,256] @ Bt[n,k]^T), BM=BN=128, BK=64
// bf16x3 split: D = Ah*Bh + Al*Bh + Ah*Bl  (fp32 accum)
// 256 threads (8 warps, warp tile 32m x 64n). grid (N/128, ceil(M/128)).
// SMEM: A double buffer 4x16KB @ SM_A, B all 4 chunks x 2 splits @ SM_B.
// ---------------------------------------------------------------------------
static const int SM_A = 0;
static const int SM_B = 4 * 16384;                    // 65536
static const int GEMM_SMEM = SM_B + 8 * 16384 + 1024; // 197632

template <int MODE>
__global__ __launch_bounds__(256, 1)
void gemm_tc(const __nv_bfloat16* __restrict__ Ah, const __nv_bfloat16* __restrict__ Al,
             const __nv_bfloat16* __restrict__ Bh, const __nv_bfloat16* __restrict__ Bl,
             const float* __restrict__ bias,   // COMBINE: br ; READOUT: rbi
             const float* __restrict__ other,  // COMBINE: agg
             const float* __restrict__ bias2,  // COMBINE: b
             const int* __restrict__ gid,      // READOUT
             float* __restrict__ outF,         // PLAIN: bufA ; READOUT: T
             __nv_bfloat16* __restrict__ outH, __nv_bfloat16* __restrict__ outL, // COMBINE
             int M)
{
    extern __shared__ char smem_raw[];
    uint32_t sb = (smem_u32(smem_raw) + 1023) & ~1023u;
    const int t = threadIdx.x;
    const int lane = t & 31;
    const int wid = t >> 5;
    const int rowBase = blockIdx.y * 128;
    const int colBase = blockIdx.x * 128;

    const int m0 = (wid & 3) * 32;      // warp m origin in CTA tile
    const int n0 = (wid >> 2) * 64;     // warp n origin

    // ldmatrix per-lane addressing components
    const int ar = (lane & 7) + ((lane >> 3) & 1) * 8;   // A row-in-16tile
    const int ak = ((lane >> 4) & 1) * 8;                // A k half
    const int br_ = (lane & 7) + ((lane >> 4) & 1) * 8;  // B n-in-16tile
    const int bk = ((lane >> 3) & 1) * 8;                // B k half

    // ---- preload all B (4 chunks x 2 splits, 8192 x 16B) ----
    {
        const __nv_bfloat16* Bsrc[2] = { Bh, Bl };
        #pragma unroll 8
        for (int i = 0; i < 32; i++) {
            int idx = i * 256 + t;
            int tile = idx >> 10;                // chunk*2 + split
            int chunk = tile >> 1, split = tile & 1;
            int w = idx & 1023;
            int nrow = w >> 3, seg = w & 7;
            uint32_t sa = sb + SM_B + tile * 16384 + swz(nrow * 128 + seg * 16);
            const __nv_bfloat16* gp = Bsrc[split] + (size_t)(colBase + nrow) * 256 + chunk * 64 + seg * 8;
            cpa16(sa, gp, 16);
        }
    }
    const __nv_bfloat16* Asrc[2] = { Ah, Al };
    auto loadA = [&](int c, int buf) {
        #pragma unroll 8
        for (int i = 0; i < 8; i++) {
            int idx = i * 256 + t;               // 0..2047
            int split = idx >> 10;
            int w = idx & 1023;
            int row = w >> 3, seg = w & 7;
            int gr = rowBase + row;
            int ok = gr < M;
            uint32_t sa = sb + SM_A + (buf * 2 + split) * 16384 + swz(row * 128 + seg * 16);
            const __nv_bfloat16* gp = Asrc[split] + (size_t)(ok ? gr : 0) * 256 + c * 64 + seg * 8;
            cpa16(sa, gp, ok ? 16 : 0);
        }
    };
    loadA(0, 0);
    asm volatile("cp.async.commit_group;" ::: "memory");

    float acc[2][8][4] = {};

    #pragma unroll
    for (int c = 0; c < 4; c++) {
        if (c < 3) {
            loadA(c + 1, (c + 1) & 1);
            asm volatile("cp.async.commit_group;" ::: "memory");
            asm volatile("cp.async.wait_group 1;" ::: "memory");
        } else {
            asm volatile("cp.async.wait_group 0;" ::: "memory");
        }
        __syncthreads();

        uint32_t aH = sb + SM_A + ((c & 1) * 2 + 0) * 16384;
        uint32_t aL = aH + 16384;
        uint32_t bH = sb + SM_B + (c * 2 + 0) * 16384;
        uint32_t bL = bH + 16384;

        #pragma unroll
        for (int kk = 0; kk < 64; kk += 16) {
            uint32_t ah[2][4], al[2][4], bh[4][4], bl[4][4];
            #pragma unroll
            for (int mt = 0; mt < 2; mt++) {
                uint32_t off = swz((uint32_t)(m0 + mt * 16 + ar) * 128 + (kk + ak) * 2);
                ldsm4(ah[mt], aH + off);
                ldsm4(al[mt], aL + off);
            }
            #pragma unroll
            for (int q = 0; q < 4; q++) {
                uint32_t off = swz((uint32_t)(n0 + q * 16 + br_) * 128 + (kk + bk) * 2);
                ldsm4(bh[q], bH + off);
                ldsm4(bl[q], bL + off);
            }
            #pragma unroll
            for (int mt = 0; mt < 2; mt++) {
                #pragma unroll
                for (int nt = 0; nt < 8; nt++) {
                    const uint32_t* bhp = &bh[nt >> 1][(nt & 1) * 2];
                    const uint32_t* blp = &bl[nt >> 1][(nt & 1) * 2];
                    mma16816(acc[mt][nt], ah[mt], bhp);
                    mma16816(acc[mt][nt], al[mt], bhp);
                    mma16816(acc[mt][nt], ah[mt], blp);
                }
            }
        }
        __syncthreads();   // protect A buffer before next cp.async overwrite
    }

    // ---- epilogue: regs -> SMEM staging (stride 129) -> coalesced global ----
    float* stg = (float*)(smem_raw + (sb + SM_B - smem_u32(smem_raw)));  // reuse B region
    #pragma unroll
    for (int mt = 0; mt < 2; mt++) {
        #pragma unroll
        for (int nt = 0; nt < 8; nt++) {
            int r = m0 + mt * 16 + (lane >> 2);
            int cc = n0 + nt * 8 + (lane & 3) * 2;
            stg[r * 129 + cc]           = acc[mt][nt][0];
            stg[r * 129 + cc + 1]       = acc[mt][nt][1];
            stg[(r + 8) * 129 + cc]     = acc[mt][nt][2];
            stg[(r + 8) * 129 + cc + 1] = acc[mt][nt][3];
        }
    }
    __syncthreads();

    const int col = colBase + (t & 127);
    const int cl = t & 127;
    for (int row = t >> 7; row < 128; row += 2) {
        int gr = rowBase + row;
        if (gr >= M) break;
        float v = stg[row * 129 + cl];
        if (MODE == M_PLAIN) {
            outF[(size_t)gr * 256 + col] = v;
        } else if (MODE == M_COMBINE) {
            v = relu_f(v + bias[col]) + relu_f(other[(size_t)gr * 256 + col] + bias2[col]);
            __nv_bfloat16 hi = __float2bfloat16_rn(v);
            __nv_bfloat16 lo = __float2bfloat16_rn(v - __bfloat162float(hi));
            outH[(size_t)gr * 256 + col] = hi;
            outL[(size_t)gr * 256 + col] = lo;
        } else { // M_READOUT: T[gid[gr]] += relu(v + bias)
            v = relu_f(v + bias[col]);
            atomicAdd(&outF[(size_t)gid[gr] * 256 + col], v);
        }
    }
}

// ---------------------------------------------------------------------------
// fp32 -> bf16 hi/lo split (activations)
// ---------------------------------------------------------------------------
__global__ __launch_bounds__(256)
void split_k(const float4* __restrict__ in, uint2* __restrict__ H, uint2* __restrict__ L, int n4)
{
    int i = blockIdx.x * blockDim.x + threadIdx.x;
    if (i >= n4) return;
    float4 f = in[i];
    float xs[4] = { f.x, f.y, f.z, f.w };
    union { __nv_bfloat16 b[4]; uint2 u; } hh, ll;
    #pragma unroll
    for (int j = 0; j < 4; j++) {
        __nv_bfloat16 hi = __float2bfloat16_rn(xs[j]);
        __nv_bfloat16 lo = __float2bfloat16_rn(xs[j] - __bfloat162float(hi));
        hh.b[j] = hi; ll.b[j] = lo;
    }
    H[i] = hh.u; L[i] = ll.u;
}

// Weight transpose + split:  out[n*256+k] = split(W[k*256+n])
__global__ __launch_bounds__(256)
void wsplit_t(const float* __restrict__ W, __nv_bfloat16* __restrict__ H, __nv_bfloat16* __restrict__ L)
{
    int idx = blockIdx.x * 256 + threadIdx.x;   // 65536 total
    int n = idx >> 8, k = idx & 255;
    float w = W[k * DIM + n];
    __nv_bfloat16 hi = __float2bfloat16_rn(w);
    __nv_bfloat16 lo = __float2bfloat16_rn(w - __bfloat162float(hi));
    H[idx] = hi; L[idx] = lo;
}

// ---------------------------------------------------------------------------
// Edge scatter: agg[dst[e]] += X[src[e]]   (row = 64 float4); warp per edge
// ---------------------------------------------------------------------------
__global__ __launch_bounds__(256)
void edge_scatter(const float4* __restrict__ X, const int* __restrict__ src,
                  const int* __restrict__ dst, float4* __restrict__ agg, int nE)
{
    int w = (int)((blockIdx.x * (size_t)blockDim.x + threadIdx.x) >> 5);
    int lane = threadIdx.x & 31;
    if (w >= nE) return;
    int s = __ldg(src + w);
    int d = __ldg(dst + w);
    const float4* xs = X + (size_t)s * 64;
    float4* ad = agg + (size_t)d * 64;
    float4 v0 = xs[lane];
    float4 v1 = xs[lane + 32];
    atomicAdd(ad + lane, v0);
    atomicAdd(ad + lane + 32, v1);
}

__global__ void zero_f4(float4* __restrict__ p, int n4)
{
    int i = blockIdx.x * blockDim.x + threadIdx.x;
    int stride = gridDim.x * blockDim.x;
    float4 z = make_float4(0.f, 0.f, 0.f, 0.f);
    for (; i < n4; i += stride) p[i] = z;
}
__global__ void zero_i(int* p, int n)
{
    int i = blockIdx.x * blockDim.x + threadIdx.x;
    if (i < n) p[i] = 0;
}
__global__ __launch_bounds__(256)
void hist_k(const int* __restrict__ gid, int* __restrict__ cnt, int n)
{
    int i = blockIdx.x * blockDim.x + threadIdx.x;
    if (i < n) atomicAdd(&cnt[gid[i]], 1);
}

// gsum[g,:GF] += T[g,:256] @ Ro[256,GF] + cnt[g]*rbo
__global__ __launch_bounds__(256)
void readout_small(const float* __restrict__ T, const float* __restrict__ Ro,
                   const float* __restrict__ rbo, const int* __restrict__ cnt,
                   float* __restrict__ gsum)
{
    __shared__ float sT[DIM];
    int g = blockIdx.x;
    int t = threadIdx.x;
    sT[t] = T[(size_t)g * DIM + t];
    __syncthreads();
    if (t < GF) {
        float a = 0.f;
        #pragma unroll 8
        for (int k = 0; k < DIM; k++) a += sT[k] * Ro[k * GF + t];
        gsum[(size_t)g * GF + t] += a + (float)cnt[g] * rbo[t];
    }
}

__global__ __launch_bounds__(256)
void predict_k(const float* __restrict__ gsum, const float* __restrict__ Wp,
               const float* __restrict__ bp, float* __restrict__ out)
{
    int warp = (int)((blockIdx.x * (size_t)blockDim.x + threadIdx.x) >> 5);
    int lane = threadIdx.x & 31;
    if (warp >= NG) return;
    const float* row = gsum + (size_t)warp * GF;
    float s = 0.f;
    for (int f = lane; f < GF; f += 32) s += row[f] * Wp[f];
    #pragma unroll
    for (int o = 16; o; o >>= 1) s += __shfl_xor_sync(0xffffffffu, s, o);
    if (lane == 0) out[warp] = s + bp[0];
}

// ---------------------------------------------------------------------------
extern "C" void kernel_launch(void* const* d_in, const int* in_sizes, int n_in,
                              void* d_out, int out_size)
{
    const float* nf[2]  = { (const float*)d_in[0], (const float*)d_in[2] };
    const int*   src[2] = { (const int*)d_in[4],   (const int*)d_in[7] };
    const int*   dst[2] = { (const int*)d_in[5],   (const int*)d_in[8] };
    const int*   gid[2] = { (const int*)d_in[6],   (const int*)d_in[9] };
    const float* W[2]   = { (const float*)d_in[10], (const float*)d_in[14] };
    const float* b[2]   = { (const float*)d_in[11], (const float*)d_in[15] };
    const float* Wr[2]  = { (const float*)d_in[12], (const float*)d_in[16] };
    const float* br[2]  = { (const float*)d_in[13], (const float*)d_in[17] };
    const float* Ri[2]  = { (const float*)d_in[18], (const float*)d_in[22] };
    const float* rbi[2] = { (const float*)d_in[19], (const float*)d_in[23] };
    const float* Ro[2]  = { (const float*)d_in[20], (const float*)d_in[24] };
    const float* rbo[2] = { (const float*)d_in[21], (const float*)d_in[25] };
    const float* Wp = (const float*)d_in[26];
    const float* bp = (const float*)d_in[27];
    float* out = (float*)d_out;

    float *bufA, *bufB, *T, *gsum;
    __nv_bfloat16 *Ahp, *Alp, *Chp, *Clp, *Wt;
    int* cnt;
    cudaGetSymbolAddress((void**)&bufA, g_bufA);
    cudaGetSymbolAddress((void**)&bufB, g_bufB);
    cudaGetSymbolAddress((void**)&Ahp, g_Ah);
    cudaGetSymbolAddress((void**)&Alp, g_Al);
    cudaGetSymbolAddress((void**)&Chp, g_Ch);
    cudaGetSymbolAddress((void**)&Clp, g_Cl);
    cudaGetSymbolAddress((void**)&Wt, g_Wt);
    cudaGetSymbolAddress((void**)&T, g_T);
    cudaGetSymbolAddress((void**)&gsum, g_gsum);
    cudaGetSymbolAddress((void**)&cnt, g_cnt);

    auto wt = [&](int m, int s) { return Wt + ((size_t)m * 2 + s) * DIM * DIM; };

    cudaFuncSetAttribute(gemm_tc<M_PLAIN>,   cudaFuncAttributeMaxDynamicSharedMemorySize, GEMM_SMEM);
    cudaFuncSetAttribute(gemm_tc<M_COMBINE>, cudaFuncAttributeMaxDynamicSharedMemorySize, GEMM_SMEM);
    cudaFuncSetAttribute(gemm_tc<M_READOUT>, cudaFuncAttributeMaxDynamicSharedMemorySize, GEMM_SMEM);

    // weight prep: transpose + bf16 split (W, Wr, Ri per branch)
    const float* wsrc[6] = { W[0], Wr[0], Ri[0], W[1], Wr[1], Ri[1] };
    for (int m = 0; m < 6; m++)
        wsplit_t<<<256, 256>>>(wsrc[m], wt(m, 0), wt(m, 1));

    zero_f4<<<64, 256>>>((float4*)gsum, NG * GF / 4);

    const dim3 gridG(2, (NN + 127) / 128);   // (2, 391)
    const int n4 = NN * DIM / 4;

    for (int k = 0; k < 2; k++) {
        // split h
        split_k<<<(n4 + 255) / 256, 256>>>((const float4*)nf[k], (uint2*)Ahp, (uint2*)Alp, n4);
        // hW = h @ W -> bufA (fp32)
        gemm_tc<M_PLAIN><<<gridG, 256, GEMM_SMEM>>>(Ahp, Alp, wt(k * 3 + 0, 0), wt(k * 3 + 0, 1),
                                                    nullptr, nullptr, nullptr, nullptr,
                                                    bufA, nullptr, nullptr, NN);
        // agg
        zero_f4<<<2048, 256>>>((float4*)bufB, n4);
        edge_scatter<<<(NE * 32 + 255) / 256, 256>>>((const float4*)bufA, src[k], dst[k],
                                                     (float4*)bufB, NE);
        // h1 = relu(h@Wr+br) + relu(agg+b) -> split into Ch/Cl
        gemm_tc<M_COMBINE><<<gridG, 256, GEMM_SMEM>>>(Ahp, Alp, wt(k * 3 + 1, 0), wt(k * 3 + 1, 1),
                                                      br[k], bufB, b[k], nullptr,
                                                      nullptr, Chp, Clp, NN);
        // T = segment_sum(relu(h1@Ri+rbi))
        zero_f4<<<128, 256>>>((float4*)T, NG * DIM / 4);
        gemm_tc<M_READOUT><<<gridG, 256, GEMM_SMEM>>>(Chp, Clp, wt(k * 3 + 2, 0), wt(k * 3 + 2, 1),
                                                      rbi[k], nullptr, nullptr, gid[k],
                                                      T, nullptr, nullptr, NN);
        // counts + small readout GEMM into gsum
        zero_i<<<2, 256>>>(cnt, NG);
        hist_k<<<(NN + 255) / 256, 256>>>(gid[k], cnt, NN);
        readout_small<<<NG, 256>>>(T, Ro[k], rbo[k], cnt, gsum);
    }

    predict_k<<<(NG * 32 + 255) / 256, 256>>>(gsum, Wp, bp, out);
}

// round 4
// speedup vs baseline: 2.2653x; 1.4965x over previous
#include <cuda_runtime.h>
#include <cuda_bf16.h>
#include <cstdint>

#define NN 50000
#define NE 800000
#define DIM 256
#define GF 200
#define NG 512

// ---------------------------------------------------------------------------
// Scratch (__device__ globals; no allocations allowed)
// ---------------------------------------------------------------------------
__device__ float g_bufA[(size_t)NN * DIM];            // hW (fp32)
__device__ float g_bufB[(size_t)NN * DIM];            // agg (fp32)
__device__ float g_bufR[(size_t)NN * DIM];            // relu(h@Wr+br)
__device__ __nv_bfloat16 g_Ah[(size_t)NN * DIM];      // h split hi
__device__ __nv_bfloat16 g_Al[(size_t)NN * DIM];      // h split lo
__device__ __nv_bfloat16 g_Ch[(size_t)NN * DIM];      // h1 split hi
__device__ __nv_bfloat16 g_Cl[(size_t)NN * DIM];      // h1 split lo
__device__ __nv_bfloat16 g_WtH[6 * DIM * DIM];        // weight slabs hi: W0,Wr0,Ri0,W1,Wr1,Ri1
__device__ __nv_bfloat16 g_WtL[6 * DIM * DIM];        // weight slabs lo
__device__ float g_T[NG * DIM];
__device__ float g_gsum[NG * GF];
__device__ int   g_cnt[NG];
// CSR scratch
__device__ int g_deg[NN];
__device__ int g_part[NN];
__device__ int g_rowptr[NN + 1];
__device__ int g_woff[NN];
__device__ int g_bsum[64];
__device__ int g_eidsrc[NE];

enum { M_DUAL = 0, M_READOUT = 1 };

__device__ __forceinline__ float relu_f(float x) { return x > 0.f ? x : 0.f; }

__device__ __forceinline__ uint32_t smem_u32(const void* p) {
    uint32_t a;
    asm("{ .reg .u64 t; cvta.to.shared.u64 t, %1; cvt.u32.u64 %0, t; }" : "=r"(a) : "l"(p));
    return a;
}
__device__ __forceinline__ uint32_t swz(uint32_t off) { return off ^ ((off >> 3) & 0x70); }
__device__ __forceinline__ void cpa16(uint32_t s, const void* g, int sz) {
    asm volatile("cp.async.cg.shared.global [%0], [%1], 16, %2;" :: "r"(s), "l"(g), "r"(sz) : "memory");
}
__device__ __forceinline__ void ldsm4(uint32_t* r, uint32_t addr) {
    asm volatile("ldmatrix.sync.aligned.m8n8.x4.shared.b16 {%0,%1,%2,%3}, [%4];"
        : "=r"(r[0]), "=r"(r[1]), "=r"(r[2]), "=r"(r[3]) : "r"(addr));
}
__device__ __forceinline__ void mma16816(float* c, const uint32_t* a, const uint32_t* b) {
    asm volatile("mma.sync.aligned.m16n8k16.row.col.f32.bf16.bf16.f32 "
        "{%0,%1,%2,%3}, {%4,%5,%6,%7}, {%8,%9}, {%0,%1,%2,%3};"
        : "+f"(c[0]), "+f"(c[1]), "+f"(c[2]), "+f"(c[3])
        : "r"(a[0]), "r"(a[1]), "r"(a[2]), "r"(a[3]), "r"(b[0]), "r"(b[1]));
}

// ---------------------------------------------------------------------------
// HMMA GEMM: BM=128, BN=128, BK=64, 512 threads (16 warps, warp tile 32x32).
// bf16x3 split: D = Ah*Bh + Al*Bh + Ah*Bl  (fp32 accum), term-major ordering.
// B slab layout: [n, k] row-major, n may span multiple concatenated matrices.
// ---------------------------------------------------------------------------
static const int SM_A = 0;                             // 2buf x 2spl x 16KB = 64KB
static const int SM_B = 4 * 16384;                     // 8 tiles x 16KB = 128KB
static const int GEMM_SMEM = SM_B + 8 * 16384 + 1024;  // 197632

template <int MODE>
__global__ __launch_bounds__(512, 1)
void gemm_tc(const __nv_bfloat16* __restrict__ Ah, const __nv_bfloat16* __restrict__ Al,
             const __nv_bfloat16* __restrict__ Bh, const __nv_bfloat16* __restrict__ Bl,
             const float* __restrict__ bias,   // DUAL: br (cols 256..511) ; READOUT: rbi
             const int* __restrict__ gid,      // READOUT
             float* __restrict__ outF,         // DUAL: bufA ; READOUT: T
             float* __restrict__ outR,         // DUAL: bufR
             int M)
{
    extern __shared__ char smem_raw[];
    uint32_t sb = (smem_u32(smem_raw) + 1023) & ~1023u;
    const int t = threadIdx.x;
    const int lane = t & 31;
    const int wid = t >> 5;
    const int rowBase = blockIdx.y * 128;
    const int colBase = blockIdx.x * 128;

    const int m0 = (wid & 3) * 32;
    const int n0 = (wid >> 2) * 32;

    const int ar = (lane & 7) + ((lane >> 3) & 1) * 8;
    const int ak = ((lane >> 4) & 1) * 8;
    const int br_ = (lane & 7) + ((lane >> 4) & 1) * 8;
    const int bk = ((lane >> 3) & 1) * 8;

    // ---- preload all B (4 chunks x 2 splits, 8192 x 16B) ----
    {
        const __nv_bfloat16* Bsrc[2] = { Bh, Bl };
        #pragma unroll 4
        for (int i = 0; i < 16; i++) {
            int idx = i * 512 + t;
            int tile = idx >> 10;                // chunk*2 + split
            int chunk = tile >> 1, split = tile & 1;
            int w = idx & 1023;
            int nrow = w >> 3, seg = w & 7;
            uint32_t sa = sb + SM_B + tile * 16384 + swz(nrow * 128 + seg * 16);
            const __nv_bfloat16* gp = Bsrc[split] + (size_t)(colBase + nrow) * 256 + chunk * 64 + seg * 8;
            cpa16(sa, gp, 16);
        }
    }
    const __nv_bfloat16* Asrc[2] = { Ah, Al };
    auto loadA = [&](int c, int buf) {
        #pragma unroll 4
        for (int i = 0; i < 4; i++) {
            int idx = i * 512 + t;               // 0..2047
            int split = idx >> 10;
            int w = idx & 1023;
            int row = w >> 3, seg = w & 7;
            int gr = rowBase + row;
            int ok = gr < M;
            uint32_t sa = sb + SM_A + (buf * 2 + split) * 16384 + swz(row * 128 + seg * 16);
            const __nv_bfloat16* gp = Asrc[split] + (size_t)(ok ? gr : 0) * 256 + c * 64 + seg * 8;
            cpa16(sa, gp, ok ? 16 : 0);
        }
    };
    loadA(0, 0);
    asm volatile("cp.async.commit_group;" ::: "memory");

    float acc[2][4][4] = {};

    #pragma unroll
    for (int c = 0; c < 4; c++) {
        if (c < 3) {
            loadA(c + 1, (c + 1) & 1);
            asm volatile("cp.async.commit_group;" ::: "memory");
            asm volatile("cp.async.wait_group 1;" ::: "memory");
        } else {
            asm volatile("cp.async.wait_group 0;" ::: "memory");
        }
        __syncthreads();

        uint32_t aH = sb + SM_A + ((c & 1) * 2 + 0) * 16384;
        uint32_t aL = aH + 16384;
        uint32_t bH = sb + SM_B + (c * 2 + 0) * 16384;
        uint32_t bL = bH + 16384;

        #pragma unroll
        for (int kk = 0; kk < 64; kk += 16) {
            uint32_t ah[2][4], al[2][4], bh[2][4], bl[2][4];
            #pragma unroll
            for (int mt = 0; mt < 2; mt++) {
                uint32_t off = swz((uint32_t)(m0 + mt * 16 + ar) * 128 + (kk + ak) * 2);
                ldsm4(ah[mt], aH + off);
                ldsm4(al[mt], aL + off);
            }
            #pragma unroll
            for (int q = 0; q < 2; q++) {
                uint32_t off = swz((uint32_t)(n0 + q * 16 + br_) * 128 + (kk + bk) * 2);
                ldsm4(bh[q], bH + off);
                ldsm4(bl[q], bL + off);
            }
            // term-major: all accs between successive hits on the same acc
            #pragma unroll
            for (int mt = 0; mt < 2; mt++)
                #pragma unroll
                for (int nt = 0; nt < 4; nt++)
                    mma16816(acc[mt][nt], ah[mt], &bh[nt >> 1][(nt & 1) * 2]);
            #pragma unroll
            for (int mt = 0; mt < 2; mt++)
                #pragma unroll
                for (int nt = 0; nt < 4; nt++)
                    mma16816(acc[mt][nt], al[mt], &bh[nt >> 1][(nt & 1) * 2]);
            #pragma unroll
            for (int mt = 0; mt < 2; mt++)
                #pragma unroll
                for (int nt = 0; nt < 4; nt++)
                    mma16816(acc[mt][nt], ah[mt], &bl[nt >> 1][(nt & 1) * 2]);
        }
        __syncthreads();
    }

    // ---- epilogue: regs -> SMEM staging (stride 129) -> coalesced global ----
    float* stg = (float*)(smem_raw + (sb + SM_B - smem_u32(smem_raw)));  // reuse B region
    #pragma unroll
    for (int mt = 0; mt < 2; mt++) {
        #pragma unroll
        for (int nt = 0; nt < 4; nt++) {
            int r = m0 + mt * 16 + (lane >> 2);
            int cc = n0 + nt * 8 + (lane & 3) * 2;
            stg[r * 129 + cc]           = acc[mt][nt][0];
            stg[r * 129 + cc + 1]       = acc[mt][nt][1];
            stg[(r + 8) * 129 + cc]     = acc[mt][nt][2];
            stg[(r + 8) * 129 + cc + 1] = acc[mt][nt][3];
        }
    }
    __syncthreads();

    const int cl = t & 127;
    const int col = colBase + cl;
    if (MODE == M_DUAL) {
        for (int row = t >> 7; row < 128; row += 4) {
            int gr = rowBase + row;
            if (gr >= M) break;
            float v = stg[row * 129 + cl];
            if (col < 256) {
                outF[(size_t)gr * 256 + col] = v;
            } else {
                outR[(size_t)gr * 256 + (col - 256)] = relu_f(v + bias[col - 256]);
            }
        }
    } else { // M_READOUT: T[gid] += relu(v + rbi), RLE over sorted gid
        int curg = -1;
        float s = 0.f;
        float bc = bias[col];
        for (int row = t >> 7; row < 128; row += 4) {
            int gr = rowBase + row;
            if (gr >= M) break;
            float v = relu_f(stg[row * 129 + cl] + bc);
            int g = gid[gr];
            if (g != curg) {
                if (curg >= 0) atomicAdd(&outF[(size_t)curg * 256 + col], s);
                curg = g; s = 0.f;
            }
            s += v;
        }
        if (curg >= 0) atomicAdd(&outF[(size_t)curg * 256 + col], s);
    }
}

// ---------------------------------------------------------------------------
// fp32 -> bf16 hi/lo split (activations)
// ---------------------------------------------------------------------------
__global__ __launch_bounds__(256)
void split_k(const float4* __restrict__ in, uint2* __restrict__ H, uint2* __restrict__ L, int n4)
{
    int i = blockIdx.x * blockDim.x + threadIdx.x;
    if (i >= n4) return;
    float4 f = in[i];
    float xs[4] = { f.x, f.y, f.z, f.w };
    union { __nv_bfloat16 b[4]; uint2 u; } hh, ll;
    #pragma unroll
    for (int j = 0; j < 4; j++) {
        __nv_bfloat16 hi = __float2bfloat16_rn(xs[j]);
        __nv_bfloat16 lo = __float2bfloat16_rn(xs[j] - __bfloat162float(hi));
        hh.b[j] = hi; ll.b[j] = lo;
    }
    H[i] = hh.u; L[i] = ll.u;
}

// All 6 weight transposes+splits in one launch: slab m: out[n*256+k]=split(Wm[k*256+n])
__global__ __launch_bounds__(256)
void wsplit_all(const float* __restrict__ w0, const float* __restrict__ w1,
                const float* __restrict__ w2, const float* __restrict__ w3,
                const float* __restrict__ w4, const float* __restrict__ w5,
                __nv_bfloat16* __restrict__ H, __nv_bfloat16* __restrict__ L)
{
    int idx = blockIdx.x * 256 + threadIdx.x;   // 0 .. 6*65536-1
    int m = idx >> 16;
    int rem = idx & 65535;
    int n = rem >> 8, k = rem & 255;
    const float* srcs[6] = { w0, w1, w2, w3, w4, w5 };
    float w = srcs[m][k * DIM + n];
    __nv_bfloat16 hi = __float2bfloat16_rn(w);
    __nv_bfloat16 lo = __float2bfloat16_rn(w - __bfloat162float(hi));
    H[idx] = hi; L[idx] = lo;
}

// ---------------------------------------------------------------------------
// CSR build + gather aggregation
// ---------------------------------------------------------------------------
__global__ void zero_i(int* p, int n)
{
    int i = blockIdx.x * blockDim.x + threadIdx.x;
    if (i < n) p[i] = 0;
}
__global__ __launch_bounds__(256)
void hist_k(const int* __restrict__ idxs, int* __restrict__ cnt, int n)
{
    int i = blockIdx.x * blockDim.x + threadIdx.x;
    if (i < n) atomicAdd(&cnt[idxs[i]], 1);
}
__global__ __launch_bounds__(1024)
void scan1_k(const int* __restrict__ deg, int* __restrict__ part, int* __restrict__ bsum)
{
    __shared__ int s[1024];
    int t = threadIdx.x;
    int idx = blockIdx.x * 1024 + t;
    int v = (idx < NN) ? deg[idx] : 0;
    s[t] = v;
    __syncthreads();
    #pragma unroll
    for (int off = 1; off < 1024; off <<= 1) {
        int x = (t >= off) ? s[t - off] : 0;
        __syncthreads();
        s[t] += x;
        __syncthreads();
    }
    if (idx < NN) part[idx] = s[t] - v;        // exclusive within block
    if (t == 1023) bsum[blockIdx.x] = s[1023];
}
__global__ void scan2_k(int* bsum, int nb)
{
    if (threadIdx.x == 0) {
        int run = 0;
        for (int i = 0; i < nb; i++) { int v = bsum[i]; bsum[i] = run; run += v; }
    }
}
__global__ __launch_bounds__(1024)
void scan3_k(const int* __restrict__ part, const int* __restrict__ bsum,
             int* __restrict__ rowptr, int* __restrict__ woff)
{
    int idx = blockIdx.x * 1024 + threadIdx.x;
    if (idx < NN) {
        int r = part[idx] + bsum[blockIdx.x];
        rowptr[idx] = r;
        woff[idx] = r;
    }
    if (idx == 0) rowptr[NN] = NE;
}
__global__ __launch_bounds__(256)
void fill_k(const int* __restrict__ src, const int* __restrict__ dst,
            int* __restrict__ woff, int* __restrict__ eidsrc, int n)
{
    int e = blockIdx.x * blockDim.x + threadIdx.x;
    if (e >= n) return;
    int pos = atomicAdd(&woff[dst[e]], 1);
    eidsrc[pos] = src[e];
}
// agg[n,:] = sum over incoming edges of hW[src,:]   (128 threads, 2 cols each)
__global__ __launch_bounds__(128)
void gather_k(const float* __restrict__ hW, const int* __restrict__ rowptr,
              const int* __restrict__ eidsrc, float* __restrict__ agg)
{
    int n = blockIdx.x;
    int t = threadIdx.x;
    int start = rowptr[n], end = rowptr[n + 1];
    float a0 = 0.f, a1 = 0.f, b0 = 0.f, b1 = 0.f;
    int j = start;
    for (; j + 1 < end; j += 2) {
        int s0 = __ldg(eidsrc + j);
        int s1 = __ldg(eidsrc + j + 1);
        a0 += hW[(size_t)s0 * 256 + t];
        a1 += hW[(size_t)s0 * 256 + t + 128];
        b0 += hW[(size_t)s1 * 256 + t];
        b1 += hW[(size_t)s1 * 256 + t + 128];
    }
    if (j < end) {
        int s0 = __ldg(eidsrc + j);
        a0 += hW[(size_t)s0 * 256 + t];
        a1 += hW[(size_t)s0 * 256 + t + 128];
    }
    agg[(size_t)n * 256 + t]       = a0 + b0;
    agg[(size_t)n * 256 + t + 128] = a1 + b1;
}

// h1 = relu(agg + b) + R   -> split to Ch/Cl
__global__ __launch_bounds__(256)
void combine_k(const float4* __restrict__ agg, const float4* __restrict__ R,
               const float* __restrict__ b, uint2* __restrict__ H, uint2* __restrict__ L, int n4)
{
    int i = blockIdx.x * blockDim.x + threadIdx.x;
    if (i >= n4) return;
    float4 a = agg[i];
    float4 r = R[i];
    int col = (i & 63) * 4;
    float4 bb = *(const float4*)(b + col);
    float vs[4] = { relu_f(a.x + bb.x) + r.x, relu_f(a.y + bb.y) + r.y,
                    relu_f(a.z + bb.z) + r.z, relu_f(a.w + bb.w) + r.w };
    union { __nv_bfloat16 q[4]; uint2 u; } hh, ll;
    #pragma unroll
    for (int j = 0; j < 4; j++) {
        __nv_bfloat16 hi = __float2bfloat16_rn(vs[j]);
        __nv_bfloat16 lo = __float2bfloat16_rn(vs[j] - __bfloat162float(hi));
        hh.q[j] = hi; ll.q[j] = lo;
    }
    H[i] = hh.u; L[i] = ll.u;
}

__global__ void zero_f4(float4* __restrict__ p, int n4)
{
    int i = blockIdx.x * blockDim.x + threadIdx.x;
    int stride = gridDim.x * blockDim.x;
    float4 z = make_float4(0.f, 0.f, 0.f, 0.f);
    for (; i < n4; i += stride) p[i] = z;
}

// gsum[g,:GF] += T[g,:256] @ Ro[256,GF] + cnt[g]*rbo
__global__ __launch_bounds__(256)
void readout_small(const float* __restrict__ T, const float* __restrict__ Ro,
                   const float* __restrict__ rbo, const int* __restrict__ cnt,
                   float* __restrict__ gsum)
{
    __shared__ float sT[DIM];
    int g = blockIdx.x;
    int t = threadIdx.x;
    sT[t] = T[(size_t)g * DIM + t];
    __syncthreads();
    if (t < GF) {
        float a = 0.f;
        #pragma unroll 8
        for (int k = 0; k < DIM; k++) a += sT[k] * Ro[k * GF + t];
        gsum[(size_t)g * GF + t] += a + (float)cnt[g] * rbo[t];
    }
}

__global__ __launch_bounds__(256)
void predict_k(const float* __restrict__ gsum, const float* __restrict__ Wp,
               const float* __restrict__ bp, float* __restrict__ out)
{
    int warp = (int)((blockIdx.x * (size_t)blockDim.x + threadIdx.x) >> 5);
    int lane = threadIdx.x & 31;
    if (warp >= NG) return;
    const float* row = gsum + (size_t)warp * GF;
    float s = 0.f;
    for (int f = lane; f < GF; f += 32) s += row[f] * Wp[f];
    #pragma unroll
    for (int o = 16; o; o >>= 1) s += __shfl_xor_sync(0xffffffffu, s, o);
    if (lane == 0) out[warp] = s + bp[0];
}

// ---------------------------------------------------------------------------
extern "C" void kernel_launch(void* const* d_in, const int* in_sizes, int n_in,
                              void* d_out, int out_size)
{
    const float* nf[2]  = { (const float*)d_in[0], (const float*)d_in[2] };
    const int*   src[2] = { (const int*)d_in[4],   (const int*)d_in[7] };
    const int*   dst[2] = { (const int*)d_in[5],   (const int*)d_in[8] };
    const int*   gid[2] = { (const int*)d_in[6],   (const int*)d_in[9] };
    const float* W[2]   = { (const float*)d_in[10], (const float*)d_in[14] };
    const float* b[2]   = { (const float*)d_in[11], (const float*)d_in[15] };
    const float* Wr[2]  = { (const float*)d_in[12], (const float*)d_in[16] };
    const float* br[2]  = { (const float*)d_in[13], (const float*)d_in[17] };
    const float* Ri[2]  = { (const float*)d_in[18], (const float*)d_in[22] };
    const float* rbi[2] = { (const float*)d_in[19], (const float*)d_in[23] };
    const float* Ro[2]  = { (const float*)d_in[20], (const float*)d_in[24] };
    const float* rbo[2] = { (const float*)d_in[21], (const float*)d_in[25] };
    const float* Wp = (const float*)d_in[26];
    const float* bp = (const float*)d_in[27];
    float* out = (float*)d_out;

    float *bufA, *bufB, *bufR, *T, *gsum;
    __nv_bfloat16 *Ahp, *Alp, *Chp, *Clp, *WtH, *WtL;
    int *cnt, *deg, *part, *rowptr, *woff, *bsum, *eidsrc;
    cudaGetSymbolAddress((void**)&bufA, g_bufA);
    cudaGetSymbolAddress((void**)&bufB, g_bufB);
    cudaGetSymbolAddress((void**)&bufR, g_bufR);
    cudaGetSymbolAddress((void**)&Ahp, g_Ah);
    cudaGetSymbolAddress((void**)&Alp, g_Al);
    cudaGetSymbolAddress((void**)&Chp, g_Ch);
    cudaGetSymbolAddress((void**)&Clp, g_Cl);
    cudaGetSymbolAddress((void**)&WtH, g_WtH);
    cudaGetSymbolAddress((void**)&WtL, g_WtL);
    cudaGetSymbolAddress((void**)&T, g_T);
    cudaGetSymbolAddress((void**)&gsum, g_gsum);
    cudaGetSymbolAddress((void**)&cnt, g_cnt);
    cudaGetSymbolAddress((void**)&deg, g_deg);
    cudaGetSymbolAddress((void**)&part, g_part);
    cudaGetSymbolAddress((void**)&rowptr, g_rowptr);
    cudaGetSymbolAddress((void**)&woff, g_woff);
    cudaGetSymbolAddress((void**)&bsum, g_bsum);
    cudaGetSymbolAddress((void**)&eidsrc, g_eidsrc);

    cudaFuncSetAttribute(gemm_tc<M_DUAL>,    cudaFuncAttributeMaxDynamicSharedMemorySize, GEMM_SMEM);
    cudaFuncSetAttribute(gemm_tc<M_READOUT>, cudaFuncAttributeMaxDynamicSharedMemorySize, GEMM_SMEM);

    const int n4 = NN * DIM / 4;
    const int NB = (NN + 1023) / 1024;       // 49 scan blocks
    const dim3 gridDual(4, (NN + 127) / 128);
    const dim3 gridRo(2, (NN + 127) / 128);

    // launch 1: all weight splits (slabs: W0,Wr0,Ri0,W1,Wr1,Ri1)
    wsplit_all<<<6 * 65536 / 256, 256>>>(W[0], Wr[0], Ri[0], W[1], Wr[1], Ri[1], WtH, WtL);
    // launch 2
    zero_f4<<<64, 256>>>((float4*)gsum, NG * GF / 4);

    for (int k = 0; k < 2; k++) {
        // 3: split h
        split_k<<<(n4 + 255) / 256, 256>>>((const float4*)nf[k], (uint2*)Ahp, (uint2*)Alp, n4);
        // 4-5: degree histogram
        zero_i<<<(NN + 255) / 256, 256>>>(deg, NN);
        hist_k<<<(NE + 255) / 256, 256>>>(dst[k], deg, NE);
        // 6: dual GEMM -> bufA (hW), bufR (relu(h@Wr+br))     [profiled launch]
        gemm_tc<M_DUAL><<<gridDual, 512, GEMM_SMEM>>>(Ahp, Alp,
            WtH + (size_t)(k * 3) * 65536, WtL + (size_t)(k * 3) * 65536,
            br[k], nullptr, bufA, bufR, NN);
        // 7-10: CSR build
        scan1_k<<<NB, 1024>>>(deg, part, bsum);
        scan2_k<<<1, 32>>>(bsum, NB);
        scan3_k<<<NB, 1024>>>(part, bsum, rowptr, woff);
        fill_k<<<(NE + 255) / 256, 256>>>(src[k], dst[k], woff, eidsrc, NE);
        // 11: gather agg = sum_in hW
        gather_k<<<NN, 128>>>(bufA, rowptr, eidsrc, bufB);
        // 12: h1 = relu(agg+b) + R -> Ch/Cl
        combine_k<<<(n4 + 255) / 256, 256>>>((const float4*)bufB, (const float4*)bufR,
                                             b[k], (uint2*)Chp, (uint2*)Clp, n4);
        // 13-14: T = segment_sum(relu(h1@Ri+rbi))
        zero_f4<<<128, 256>>>((float4*)T, NG * DIM / 4);
        gemm_tc<M_READOUT><<<gridRo, 512, GEMM_SMEM>>>(Chp, Clp,
            WtH + (size_t)(k * 3 + 2) * 65536, WtL + (size_t)(k * 3 + 2) * 65536,
            rbi[k], gid[k], T, nullptr, NN);
        // 15-17: counts + small readout into gsum
        zero_i<<<2, 256>>>(cnt, NG);
        hist_k<<<(NN + 255) / 256, 256>>>(gid[k], cnt, NN);
        readout_small<<<NG, 256>>>(T, Ro[k], rbo[k], cnt, gsum);
    }

    predict_k<<<(NG * 32 + 255) / 256, 256>>>(gsum, Wp, bp, out);
}